// round 2
// baseline (speedup 1.0000x reference)
#include <cuda_runtime.h>

#define NREL 8
#define NU   50000
#define NTOT 160000
#define ETOT 3400000
typedef long long ll;

__constant__ int c_N[8]       = {50000,50000,10000,10000,10000,10000,10000,10000};
__constant__ int c_nodeoff[8] = {0,50000,100000,110000,120000,130000,140000,150000};
__constant__ int c_edgeoff[8] = {0,800000,1600000,1900000,2200000,2500000,2800000,3100000};
__constant__ int c_dstt[8]    = {1,0,2,3,4,5,6,7};
__constant__ int c_srct[8]    = {0,1,1,1,1,1,1,1};
__constant__ int c_chunkoff[8]= {0,782,1564,1721,1878,2035,2192,2349};

__device__ float g_emb[NTOT*64];
__device__ float g_ssrc[NREL*NU*2];
__device__ float g_sdst[NREL*NU*2];
__device__ float g_z[NREL*NU*64];
__device__ float g_r[NREL*NU*2];
__device__ int   g_rowptr[NREL*(NU+1)];
__device__ int   g_counts[NREL*NU];
__device__ int   g_cursor[NREL*NU];
__device__ int   g_isorted[ETOT];

__device__ __forceinline__ float lrelu(float x){ return x > 0.f ? x : 0.2f*x; }

// ---------------- setup ----------------
__global__ void k_zero(){
    int i = blockIdx.x*blockDim.x + threadIdx.x;
    if (i < NREL*NU){ g_counts[i]=0; g_cursor[i]=0; }
}

__global__ void k_count(const int* __restrict__ u, int E, int rel){
    int t = blockIdx.x*blockDim.x + threadIdx.x;
    if (t < E) atomicAdd(&g_counts[rel*NU + u[t]], 1);
}

__global__ void k_scan(){
    __shared__ int sm[1024];
    int rel = blockIdx.x, t = threadIdx.x;
    const int n = NU, CH = 49;
    int* cnt = g_counts + rel*NU;
    int* rp  = g_rowptr + rel*(NU+1);
    int c0 = t*CH, c1 = min(c0+CH, n);
    int s = 0;
    for (int i=c0;i<c1;i++) s += cnt[i];
    sm[t] = s; __syncthreads();
    for (int off=1; off<1024; off<<=1){
        int v = (t>=off)? sm[t-off] : 0;
        __syncthreads();
        sm[t] += v;
        __syncthreads();
    }
    int run = sm[t] - s;
    for (int i=c0;i<c1;i++){ rp[i]=run; run+=cnt[i]; }
    if (t==0) rp[n] = sm[1023];
}

__global__ void k_scatter(const int* __restrict__ u, const int* __restrict__ ia, int E, int rel){
    int t = blockIdx.x*blockDim.x + threadIdx.x;
    if (t < E){
        int uu = u[t];
        int pos = g_rowptr[rel*(NU+1)+uu] + atomicAdd(&g_cursor[rel*NU+uu], 1);
        g_isorted[c_edgeoff[rel] + pos] = ia[t];
    }
}

// initial projection: l2norm(lrelu(emb_t @ Wtk[t][k]))
__global__ void __launch_bounds__(256) k_proj(
    const float* __restrict__ e0, const float* __restrict__ e1,
    const float* __restrict__ e2, const float* __restrict__ e3,
    const float* __restrict__ e4, const float* __restrict__ e5,
    const float* __restrict__ e6, const float* __restrict__ e7,
    const float* __restrict__ Wtk)
{
    __shared__ float sW[4096];
    __shared__ float sE[4096];
    int b = blockIdx.x;
    int t = 0;
    #pragma unroll
    for (int j=1;j<8;j++) if (b >= c_chunkoff[j]) t = j;
    int n0 = (b - c_chunkoff[t]) * 64;
    const float* embp;
    switch (t){
        case 0: embp=e0; break; case 1: embp=e1; break;
        case 2: embp=e2; break; case 3: embp=e3; break;
        case 4: embp=e4; break; case 5: embp=e5; break;
        case 6: embp=e6; break; default: embp=e7; break;
    }
    int Nt = c_N[t], tid = threadIdx.x;
    for (int i=tid;i<4096;i+=256) sW[i] = Wtk[t*4096 + i];
    for (int i=tid;i<4096;i+=256){
        int n = n0 + (i>>6);
        sE[i] = (n < Nt) ? embp[(ll)n*64 + (i&63)] : 0.f;
    }
    __syncthreads();
    int lane = tid&31, w = tid>>5;
    float acc0[8], acc1[8];
    #pragma unroll
    for (int q=0;q<8;q++){ acc0[q]=0.f; acc1[q]=0.f; }
    #pragma unroll 4
    for (int c=0;c<64;c++){
        float w0 = sW[c*32+lane];
        float w1 = sW[2048+c*32+lane];
        #pragma unroll
        for (int q=0;q<8;q++){
            float e = sE[(w*8+q)*64 + c];
            acc0[q] = fmaf(e,w0,acc0[q]);
            acc1[q] = fmaf(e,w1,acc1[q]);
        }
    }
    #pragma unroll
    for (int q=0;q<8;q++){
        int n = n0 + w*8 + q;
        if (n >= Nt) continue;
        float y0 = lrelu(acc0[q]), y1 = lrelu(acc1[q]);
        float s0 = y0*y0, s1 = y1*y1;
        #pragma unroll
        for (int o=16;o;o>>=1){
            s0 += __shfl_xor_sync(0xffffffffu, s0, o);
            s1 += __shfl_xor_sync(0xffffffffu, s1, o);
        }
        float d0 = fmaxf(sqrtf(s0), 1e-12f);
        float d1 = fmaxf(sqrtf(s1), 1e-12f);
        ll bo = ((ll)c_nodeoff[t] + n) * 64;
        g_emb[bo + lane]      = y0 / d0;
        g_emb[bo + 32 + lane] = y1 / d1;
    }
}

// ---------------- per-iteration ----------------
// per-node logit halves: s[k] = emb[node][k] . a[rel][k][side-half]
__global__ void k_dots(const float* __restrict__ at){
    int lane = threadIdx.x & 31;
    int gw = (blockIdx.x*blockDim.x + threadIdx.x) >> 5;
    int combo = gw / NU, n = gw - combo*NU;
    int rel = combo >> 1, side = combo & 1;
    int type = side ? c_dstt[rel] : c_srct[rel];
    if (n >= c_N[type]) return;
    float2 e = *(const float2*)&g_emb[((ll)c_nodeoff[type]+n)*64 + lane*2];
    int k = lane >> 4;
    float2 a = *(const float2*)&at[(rel*2+k)*64 + side*32 + (lane&15)*2];
    float p = e.x*a.x + e.y*a.y;
    p += __shfl_xor_sync(0xffffffffu, p, 8);
    p += __shfl_xor_sync(0xffffffffu, p, 4);
    p += __shfl_xor_sync(0xffffffffu, p, 2);
    p += __shfl_xor_sync(0xffffffffu, p, 1);
    if ((lane&15) == 0){
        float* out = side ? g_sdst : g_ssrc;
        out[(rel*NU+n)*2 + k] = p;
    }
}

// warp per source node: segment softmax + weighted aggregation (CSR gather)
__global__ void __launch_bounds__(256) k_aggregate(){
    int tid = threadIdx.x, lane = tid&31, wl = tid>>5;
    int gw = blockIdx.x*8 + wl;
    int rel = gw / NU, n = gw - rel*NU;
    float2 ss = *(const float2*)&g_ssrc[(rel*NU+n)*2];
    int rb = rel*(NU+1)+n;
    int row = g_rowptr[rb], deg = g_rowptr[rb+1]-row;
    int eb = c_edgeoff[rel] + row;
    const float* __restrict__ sdb = g_sdst + rel*NU*2;
    // pass 1: max
    float m = -1e30f;
    for (int p=lane; p<deg; p+=32){
        int i = g_isorted[eb+p];
        float2 sd = *(const float2*)&sdb[i*2];
        float es = 0.5f*(fmaxf(ss.x+sd.x,0.f)+fmaxf(ss.y+sd.y,0.f));
        m = fmaxf(m, es);
    }
    #pragma unroll
    for (int o=16;o;o>>=1) m = fmaxf(m, __shfl_xor_sync(0xffffffffu, m, o));
    // pass 2: sum exp
    float s = 0.f;
    for (int p=lane; p<deg; p+=32){
        int i = g_isorted[eb+p];
        float2 sd = *(const float2*)&sdb[i*2];
        float es = 0.5f*(fmaxf(ss.x+sd.x,0.f)+fmaxf(ss.y+sd.y,0.f));
        s += __expf(es - m);
    }
    #pragma unroll
    for (int o=16;o;o>>=1) s += __shfl_xor_sync(0xffffffffu, s, o);
    float inv = (deg > 0) ? 1.f/s : 0.f;
    // pass 3: dim-parallel weighted gather (lane = (k,d) pair)
    const float* __restrict__ de = g_emb + (ll)c_nodeoff[c_dstt[rel]]*64;
    float ax = 0.f, ay = 0.f;
    #pragma unroll 2
    for (int p=0; p<deg; p++){
        int i = g_isorted[eb+p];
        float2 sd = *(const float2*)&sdb[i*2];
        float es = 0.5f*(fmaxf(ss.x+sd.x,0.f)+fmaxf(ss.y+sd.y,0.f));
        float w = __expf(es - m) * inv;
        float2 ev = *(const float2*)&de[(ll)i*64 + lane*2];
        ax = fmaf(w, ev.x, ax);
        ay = fmaf(w, ev.y, ay);
    }
    float2* zo = (float2*)&g_z[((ll)rel*NU+n)*64 + lane*2];
    *zo = make_float2(ax, ay);
}

// z = lrelu(z_agg) @ W ; r = softmax_k( tanh(z) . q_rela[rel] )
__global__ void __launch_bounds__(256) k_transform(const float* __restrict__ W,
                                                   const float* __restrict__ q){
    __shared__ float sW[1024];
    __shared__ float sq[256];
    int tid = threadIdx.x;
    for (int i=tid;i<1024;i+=256) sW[i] = W[i];
    if (tid < 256) sq[tid] = q[tid];
    __syncthreads();
    int lane = tid&31, wl = tid>>5;
    int gw = blockIdx.x*8 + wl;
    int rel = gw / NU, n = gw - rel*NU;
    ll zb = ((ll)rel*NU + n) * 64;
    float z0 = lrelu(g_z[zb + lane]);
    float z1 = lrelu(g_z[zb + 32 + lane]);
    float o0 = 0.f, o1 = 0.f;
    #pragma unroll
    for (int c=0;c<32;c++){
        float w = sW[c*32 + lane];
        o0 = fmaf(__shfl_sync(0xffffffffu, z0, c), w, o0);
        o1 = fmaf(__shfl_sync(0xffffffffu, z1, c), w, o1);
    }
    g_z[zb + lane] = o0;
    g_z[zb + 32 + lane] = o1;
    float qv = sq[rel*32 + lane];
    float t0 = tanhf(o0) * qv, t1 = tanhf(o1) * qv;
    #pragma unroll
    for (int o=16;o;o>>=1){
        t0 += __shfl_xor_sync(0xffffffffu, t0, o);
        t1 += __shfl_xor_sync(0xffffffffu, t1, o);
    }
    if (lane == 0){
        float r0 = 1.f / (1.f + __expf(t1 - t0));
        g_r[(rel*NU+n)*2]     = r0;
        g_r[(rel*NU+n)*2 + 1] = 1.f - r0;
    }
}

// ego update + l2norm for node types 0 and 1
__global__ void __launch_bounds__(256) k_update(){
    int tid = threadIdx.x, lane = tid&31, wl = tid>>5;
    int gw = blockIdx.x*8 + wl;          // 0..99999
    int t = (gw >= NU) ? 1 : 0;
    int n = gw - t*NU;
    ll eb = ((ll)c_nodeoff[t] + n)*64 + lane*2;
    float2 e = *(float2*)&g_emb[eb];
    int k = lane >> 4;
    int j0 = t ? 1 : 0, j1 = t ? 8 : 1;
    for (int j=j0; j<j1; j++){
        ll zb = ((ll)j*NU + n)*64 + lane*2;
        float r = g_r[((ll)j*NU + n)*2 + k];
        float2 zv = *(const float2*)&g_z[zb];
        e.x = fmaf(zv.x, r, e.x);
        e.y = fmaf(zv.y, r, e.y);
    }
    float s = e.x*e.x + e.y*e.y;
    #pragma unroll
    for (int o=8;o;o>>=1) s += __shfl_xor_sync(0xffffffffu, s, o);
    float d = fmaxf(sqrtf(s), 1e-12f);
    e.x /= d; e.y /= d;
    *(float2*)&g_emb[eb] = e;
}

__global__ void k_out(float4* __restrict__ out){
    int i = blockIdx.x*blockDim.x + threadIdx.x;
    if (i < NTOT*16) out[i] = ((const float4*)g_emb)[i];
}

// ---------------- launch ----------------
extern "C" void kernel_launch(void* const* d_in, const int* in_sizes, int n_in,
                              void* d_out, int out_size) {
    const float* emb[8];
    for (int t=0;t<8;t++) emb[t] = (const float*)d_in[t];
    const int* u[8]; const int* ia[8]; int E[8];
    for (int e=0;e<8;e++){
        u[e]  = (const int*)d_in[8 + 2*e];
        ia[e] = (const int*)d_in[9 + 2*e];
        E[e]  = in_sizes[8 + 2*e];
    }
    const float* Wtk = (const float*)d_in[24];
    const float* at  = (const float*)d_in[25];
    const float* W   = (const float*)d_in[26];
    const float* q   = (const float*)d_in[27];

    k_zero<<<(NREL*NU + 255)/256, 256>>>();
    for (int e=0;e<8;e++) k_count<<<(E[e]+255)/256, 256>>>(u[e], E[e], e);
    k_scan<<<8, 1024>>>();
    for (int e=0;e<8;e++) k_scatter<<<(E[e]+255)/256, 256>>>(u[e], ia[e], E[e], e);
    k_proj<<<2506, 256>>>(emb[0],emb[1],emb[2],emb[3],emb[4],emb[5],emb[6],emb[7], Wtk);

    for (int it=0; it<4; it++){
        k_dots<<<100000, 256>>>(at);
        k_aggregate<<<50000, 256>>>();
        k_transform<<<50000, 256>>>(W, q);
        k_update<<<12500, 256>>>();
    }
    k_out<<<(NTOT*16 + 255)/256, 256>>>((float4*)d_out);
}

// round 3
// speedup vs baseline: 1.5180x; 1.5180x over previous
#include <cuda_runtime.h>

#define NREL 8
#define NU   50000
#define NTOT 160000
#define ETOT 3400000
typedef long long ll;

__constant__ int c_N[8]       = {50000,50000,10000,10000,10000,10000,10000,10000};
__constant__ int c_nodeoff[8] = {0,50000,100000,110000,120000,130000,140000,150000};
__constant__ int c_edgeoff[8] = {0,800000,1600000,1900000,2200000,2500000,2800000,3100000};
__constant__ int c_dstt[8]    = {1,0,2,3,4,5,6,7};
__constant__ int c_chunkoff[8]= {0,782,1564,1721,1878,2035,2192,2349};

__device__ float g_emb[NTOT*64];
__device__ float g_ssrc[NREL*NU*2];
__device__ float g_sdst[NREL*NU*2];
__device__ float g_z[NREL*NU*64];
__device__ float g_r[NREL*NU*2];
__device__ int   g_rowptr[NREL*(NU+1)];
__device__ int   g_counts[NREL*NU];
__device__ int   g_cursor[NREL*NU];
__device__ int   g_isorted[ETOT];

__device__ __forceinline__ float lrelu(float x){ return x > 0.f ? x : 0.2f*x; }
__device__ __forceinline__ float tanh_f(float x){
    float y; asm("tanh.approx.f32 %0, %1;" : "=f"(y) : "f"(x)); return y;
}

// ---------------- setup ----------------
__global__ void k_zero(){
    int i = blockIdx.x*blockDim.x + threadIdx.x;
    if (i < NREL*NU){ g_counts[i]=0; g_cursor[i]=0; }
}

__global__ void k_count_all(const int* __restrict__ u0, const int* __restrict__ u1,
                            const int* __restrict__ u2, const int* __restrict__ u3,
                            const int* __restrict__ u4, const int* __restrict__ u5,
                            const int* __restrict__ u6, const int* __restrict__ u7){
    int t = blockIdx.x*blockDim.x + threadIdx.x;
    if (t >= ETOT) return;
    int rel = 0;
    #pragma unroll
    for (int j=1;j<8;j++) if (t >= c_edgeoff[j]) rel = j;
    const int* up;
    switch (rel){
        case 0: up=u0; break; case 1: up=u1; break; case 2: up=u2; break; case 3: up=u3; break;
        case 4: up=u4; break; case 5: up=u5; break; case 6: up=u6; break; default: up=u7; break;
    }
    atomicAdd(&g_counts[rel*NU + up[t - c_edgeoff[rel]]], 1);
}

__global__ void k_scan(){
    __shared__ int sm[1024];
    int rel = blockIdx.x, t = threadIdx.x;
    const int n = NU, CH = 49;
    int* cnt = g_counts + rel*NU;
    int* rp  = g_rowptr + rel*(NU+1);
    int c0 = t*CH, c1 = min(c0+CH, n);
    int s = 0;
    for (int i=c0;i<c1;i++) s += cnt[i];
    sm[t] = s; __syncthreads();
    for (int off=1; off<1024; off<<=1){
        int v = (t>=off)? sm[t-off] : 0;
        __syncthreads();
        sm[t] += v;
        __syncthreads();
    }
    int run = sm[t] - s;
    for (int i=c0;i<c1;i++){ rp[i]=run; run+=cnt[i]; }
    if (t==0) rp[n] = sm[1023];
}

__global__ void k_scatter_all(const int* __restrict__ u0, const int* __restrict__ u1,
                              const int* __restrict__ u2, const int* __restrict__ u3,
                              const int* __restrict__ u4, const int* __restrict__ u5,
                              const int* __restrict__ u6, const int* __restrict__ u7,
                              const int* __restrict__ i0, const int* __restrict__ i1,
                              const int* __restrict__ i2, const int* __restrict__ i3,
                              const int* __restrict__ i4, const int* __restrict__ i5,
                              const int* __restrict__ i6, const int* __restrict__ i7){
    int t = blockIdx.x*blockDim.x + threadIdx.x;
    if (t >= ETOT) return;
    int rel = 0;
    #pragma unroll
    for (int j=1;j<8;j++) if (t >= c_edgeoff[j]) rel = j;
    const int *up, *ip;
    switch (rel){
        case 0: up=u0; ip=i0; break; case 1: up=u1; ip=i1; break;
        case 2: up=u2; ip=i2; break; case 3: up=u3; ip=i3; break;
        case 4: up=u4; ip=i4; break; case 5: up=u5; ip=i5; break;
        case 6: up=u6; ip=i6; break; default: up=u7; ip=i7; break;
    }
    int e = t - c_edgeoff[rel];
    int uu = up[e];
    int pos = g_rowptr[rel*(NU+1)+uu] + atomicAdd(&g_cursor[rel*NU+uu], 1);
    g_isorted[c_edgeoff[rel] + pos] = ip[e];
}

// initial projection: l2norm(lrelu(emb_t @ Wtk[t][k]))
__global__ void __launch_bounds__(256) k_proj(
    const float* __restrict__ e0, const float* __restrict__ e1,
    const float* __restrict__ e2, const float* __restrict__ e3,
    const float* __restrict__ e4, const float* __restrict__ e5,
    const float* __restrict__ e6, const float* __restrict__ e7,
    const float* __restrict__ Wtk)
{
    __shared__ float sW[4096];
    __shared__ float sE[4096];
    int b = blockIdx.x;
    int t = 0;
    #pragma unroll
    for (int j=1;j<8;j++) if (b >= c_chunkoff[j]) t = j;
    int n0 = (b - c_chunkoff[t]) * 64;
    const float* embp;
    switch (t){
        case 0: embp=e0; break; case 1: embp=e1; break;
        case 2: embp=e2; break; case 3: embp=e3; break;
        case 4: embp=e4; break; case 5: embp=e5; break;
        case 6: embp=e6; break; default: embp=e7; break;
    }
    int Nt = c_N[t], tid = threadIdx.x;
    for (int i=tid;i<4096;i+=256) sW[i] = Wtk[t*4096 + i];
    for (int i=tid;i<4096;i+=256){
        int n = n0 + (i>>6);
        sE[i] = (n < Nt) ? embp[(ll)n*64 + (i&63)] : 0.f;
    }
    __syncthreads();
    int lane = tid&31, w = tid>>5;
    float acc0[8], acc1[8];
    #pragma unroll
    for (int q=0;q<8;q++){ acc0[q]=0.f; acc1[q]=0.f; }
    #pragma unroll 4
    for (int c=0;c<64;c++){
        float w0 = sW[c*32+lane];
        float w1 = sW[2048+c*32+lane];
        #pragma unroll
        for (int q=0;q<8;q++){
            float e = sE[(w*8+q)*64 + c];
            acc0[q] = fmaf(e,w0,acc0[q]);
            acc1[q] = fmaf(e,w1,acc1[q]);
        }
    }
    #pragma unroll
    for (int q=0;q<8;q++){
        int n = n0 + w*8 + q;
        if (n >= Nt) continue;
        float y0 = lrelu(acc0[q]), y1 = lrelu(acc1[q]);
        float s0 = y0*y0, s1 = y1*y1;
        #pragma unroll
        for (int o=16;o;o>>=1){
            s0 += __shfl_xor_sync(0xffffffffu, s0, o);
            s1 += __shfl_xor_sync(0xffffffffu, s1, o);
        }
        float d0 = fmaxf(sqrtf(s0), 1e-12f);
        float d1 = fmaxf(sqrtf(s1), 1e-12f);
        ll bo = ((ll)c_nodeoff[t] + n) * 64;
        g_emb[bo + lane]      = y0 / d0;
        g_emb[bo + 32 + lane] = y1 / d1;
    }
}

// initial dots (all 16 (rel,side) combos; types 2-7 never change afterwards)
__global__ void k_dots(const float* __restrict__ at){
    int lane = threadIdx.x & 31;
    int gw = (blockIdx.x*blockDim.x + threadIdx.x) >> 5;
    int combo = gw / NU, n = gw - combo*NU;
    int rel = combo >> 1, side = combo & 1;
    int type = side ? c_dstt[rel] : (rel ? 1 : 0);
    if (n >= c_N[type]) return;
    float2 e = *(const float2*)&g_emb[((ll)c_nodeoff[type]+n)*64 + lane*2];
    int k = lane >> 4;
    float2 a = *(const float2*)&at[(rel*2+k)*64 + side*32 + (lane&15)*2];
    float p = e.x*a.x + e.y*a.y;
    p += __shfl_xor_sync(0xffffffffu, p, 8);
    p += __shfl_xor_sync(0xffffffffu, p, 4);
    p += __shfl_xor_sync(0xffffffffu, p, 2);
    p += __shfl_xor_sync(0xffffffffu, p, 1);
    if ((lane&15) == 0){
        float* out = side ? g_sdst : g_ssrc;
        out[(rel*NU+n)*2 + k] = p;
    }
}

// ---------------- fused per-iteration kernels ----------------
// warp per source node: softmax (no max, logits bounded) + gather + z@W + r
__global__ void __launch_bounds__(256) k_agg(const float* __restrict__ W,
                                             const float* __restrict__ q){
    __shared__ float sW[1024];
    __shared__ float sEw[8][128];
    __shared__ int   sEi[8][128];
    int tid = threadIdx.x;
    for (int i=tid;i<1024;i+=256) sW[i] = W[i];
    __syncthreads();
    int lane = tid&31, wl = tid>>5;
    int gw = blockIdx.x*8 + wl;
    int rel = gw / NU, n = gw - rel*NU;
    float2 ss = *(const float2*)&g_ssrc[(rel*NU+n)*2];
    int rb = rel*(NU+1)+n;
    int row = g_rowptr[rb], deg = g_rowptr[rb+1]-row;
    int eb = c_edgeoff[rel] + row;
    const float* __restrict__ sdb = g_sdst + rel*NU*2;
    const float* __restrict__ de  = g_emb + (ll)c_nodeoff[c_dstt[rel]]*64;

    // pass A: per-edge exp(logit) -> smem cache + sum  (bounded logits: no max pass)
    float s = 0.f;
    for (int p=lane; p<deg; p+=32){
        int i = g_isorted[eb+p];
        float2 sd = *(const float2*)&sdb[i*2];
        float es = 0.5f*(fmaxf(ss.x+sd.x,0.f)+fmaxf(ss.y+sd.y,0.f));
        float w = __expf(es);
        if (p < 128){ sEw[wl][p]=w; sEi[wl][p]=i; }
        s += w;
    }
    #pragma unroll
    for (int o=16;o;o>>=1) s += __shfl_xor_sync(0xffffffffu, s, o);
    float inv = (deg > 0) ? __fdividef(1.f, s) : 0.f;
    __syncwarp();

    // pass B: weighted gather, chunked for MLP
    float ax=0.f, ay=0.f, bx=0.f, by=0.f;
    int dcap = deg < 128 ? deg : 128;
    int p = 0;
    for (; p+8 <= dcap; p += 8){
        int ii[8]; float ww[8];
        #pragma unroll
        for (int j=0;j<8;j++){ ii[j]=sEi[wl][p+j]; ww[j]=sEw[wl][p+j]; }
        float2 ev[8];
        #pragma unroll
        for (int j=0;j<8;j++) ev[j] = *(const float2*)&de[ii[j]*64 + lane*2];
        #pragma unroll
        for (int j=0;j<8;j++){
            if (j&1){ bx=fmaf(ww[j],ev[j].x,bx); by=fmaf(ww[j],ev[j].y,by); }
            else    { ax=fmaf(ww[j],ev[j].x,ax); ay=fmaf(ww[j],ev[j].y,ay); }
        }
    }
    for (; p<dcap; p++){
        int i = sEi[wl][p]; float w = sEw[wl][p];
        float2 ev = *(const float2*)&de[i*64 + lane*2];
        ax = fmaf(w,ev.x,ax); ay = fmaf(w,ev.y,ay);
    }
    for (; p<deg; p++){  // rare deg>128 fallback (recompute)
        int i = g_isorted[eb+p];
        float2 sd = *(const float2*)&sdb[i*2];
        float es = 0.5f*(fmaxf(ss.x+sd.x,0.f)+fmaxf(ss.y+sd.y,0.f));
        float w = __expf(es);
        float2 ev = *(const float2*)&de[i*64 + lane*2];
        ax = fmaf(w,ev.x,ax); ay = fmaf(w,ev.y,ay);
    }
    ax = (ax+bx)*inv; ay = (ay+by)*inv;

    // fused transform: o = lrelu(z) @ W  (per factor, shuffle matmul)
    float zx = lrelu(ax), zy = lrelu(ay);
    int col = (lane&15)*2, base = lane & 16;
    float ox = 0.f, oy = 0.f;
    #pragma unroll
    for (int c=0;c<32;c++){
        float zc = __shfl_sync(0xffffffffu, (c&1)? zy : zx, base + (c>>1));
        ox = fmaf(zc, sW[c*32+col],   ox);
        oy = fmaf(zc, sW[c*32+col+1], oy);
    }
    ll zb = ((ll)rel*NU + n)*64;
    *(float2*)&g_z[zb + lane*2] = make_float2(ox, oy);

    // r = softmax_k( tanh(o) . q[rel] )
    float t = tanh_f(ox)*__ldg(&q[rel*32+col]) + tanh_f(oy)*__ldg(&q[rel*32+col+1]);
    #pragma unroll
    for (int o=8;o;o>>=1) t += __shfl_xor_sync(0xffffffffu, t, o);
    float to = __shfl_xor_sync(0xffffffffu, t, 16);
    if ((lane&15) == 0)
        g_r[(rel*NU+n)*2 + (lane>>4)] = __fdividef(1.f, 1.f + __expf(to - t));
}

// ego update + per-factor l2norm + fused dots for next iteration
__global__ void __launch_bounds__(256) k_upd(const float* __restrict__ at){
    int tid = threadIdx.x, lane = tid&31, wl = tid>>5;
    int gw = blockIdx.x*8 + wl;          // 0..99999
    int t = (gw >= NU) ? 1 : 0;
    int n = gw - t*NU;
    ll eb = ((ll)c_nodeoff[t] + n)*64 + lane*2;
    float2 e = *(float2*)&g_emb[eb];
    int k = lane >> 4, col = (lane&15)*2;
    int j0 = t ? 1 : 0, j1 = t ? 8 : 1;
    for (int j=j0; j<j1; j++){
        float r = g_r[((ll)j*NU + n)*2 + k];
        float2 zv = *(const float2*)&g_z[((ll)j*NU + n)*64 + lane*2];
        e.x = fmaf(zv.x, r, e.x);
        e.y = fmaf(zv.y, r, e.y);
    }
    float s = e.x*e.x + e.y*e.y;
    #pragma unroll
    for (int o=8;o;o>>=1) s += __shfl_xor_sync(0xffffffffu, s, o);
    float d = fmaxf(sqrtf(s), 1e-12f);
    float dinv = __fdividef(1.f, d);
    e.x *= dinv; e.y *= dinv;
    *(float2*)&g_emb[eb] = e;

    // fused per-node dots for next iteration (only types 0/1 ever change)
    if (t == 0){
        float p0 = e.x*__ldg(&at[k*64+col])        + e.y*__ldg(&at[k*64+col+1]);        // rel0 src
        float p1 = e.x*__ldg(&at[128+k*64+32+col]) + e.y*__ldg(&at[128+k*64+32+col+1]); // rel1 dst
        #pragma unroll
        for (int o=8;o;o>>=1){
            p0 += __shfl_xor_sync(0xffffffffu, p0, o);
            p1 += __shfl_xor_sync(0xffffffffu, p1, o);
        }
        if ((lane&15) == 0){
            g_ssrc[n*2 + k]        = p0;
            g_sdst[(NU+n)*2 + k]   = p1;
        }
    } else {
        float p[8];
        p[0] = e.x*__ldg(&at[k*64+32+col]) + e.y*__ldg(&at[k*64+32+col+1]);             // rel0 dst
        #pragma unroll
        for (int rl=1; rl<8; rl++)
            p[rl] = e.x*__ldg(&at[rl*128+k*64+col]) + e.y*__ldg(&at[rl*128+k*64+col+1]); // src
        #pragma unroll
        for (int rl=0; rl<8; rl++){
            #pragma unroll
            for (int o=8;o;o>>=1) p[rl] += __shfl_xor_sync(0xffffffffu, p[rl], o);
        }
        if ((lane&15) == 0){
            g_sdst[n*2 + k] = p[0];
            #pragma unroll
            for (int rl=1; rl<8; rl++) g_ssrc[(rl*NU+n)*2 + k] = p[rl];
        }
    }
}

__global__ void k_out(float4* __restrict__ out){
    int i = blockIdx.x*blockDim.x + threadIdx.x;
    if (i < NTOT*16) out[i] = ((const float4*)g_emb)[i];
}

// ---------------- launch ----------------
extern "C" void kernel_launch(void* const* d_in, const int* in_sizes, int n_in,
                              void* d_out, int out_size) {
    const float* emb[8];
    for (int t=0;t<8;t++) emb[t] = (const float*)d_in[t];
    const int* u[8]; const int* ia[8];
    for (int e=0;e<8;e++){
        u[e]  = (const int*)d_in[8 + 2*e];
        ia[e] = (const int*)d_in[9 + 2*e];
    }
    const float* Wtk = (const float*)d_in[24];
    const float* at  = (const float*)d_in[25];
    const float* W   = (const float*)d_in[26];
    const float* q   = (const float*)d_in[27];

    k_zero<<<(NREL*NU + 255)/256, 256>>>();
    k_count_all<<<(ETOT+255)/256, 256>>>(u[0],u[1],u[2],u[3],u[4],u[5],u[6],u[7]);
    k_scan<<<8, 1024>>>();
    k_scatter_all<<<(ETOT+255)/256, 256>>>(u[0],u[1],u[2],u[3],u[4],u[5],u[6],u[7],
                                           ia[0],ia[1],ia[2],ia[3],ia[4],ia[5],ia[6],ia[7]);
    k_proj<<<2506, 256>>>(emb[0],emb[1],emb[2],emb[3],emb[4],emb[5],emb[6],emb[7], Wtk);
    k_dots<<<100000, 256>>>(at);

    for (int it=0; it<4; it++){
        k_agg<<<50000, 256>>>(W, q);
        k_upd<<<12500, 256>>>(at);
    }
    k_out<<<(NTOT*16 + 255)/256, 256>>>((float4*)d_out);
}